// round 3
// baseline (speedup 1.0000x reference)
#include <cuda_runtime.h>
#include <math.h>

// Problem constants (fixed by setup_inputs)
#define BB   4
#define C2   512        // deep channels
#define DD   32         // d = 2*C/16
#define HWD  4096       // 64*64 deep spatial
#define OC   256        // out channels of K conv
#define CIN  256        // shallow channels
#define PIX  16384      // 128*128 shallow spatial

// Scratch (device globals: allocation-free)
__device__ float g_maxout[BB * DD * HWD];            // [b][dd][p]
__device__ float g_qmax [BB * HWD];
__device__ float g_qmean[BB * HWD];
__device__ float g_scale[BB * HWD];                  // 1 + sigmoid(re_score)
__device__ float g_Kx[(size_t)BB * OC * PIX];        // [b][o][128*128], 64MB

// ---------------------------------------------------------------------------
// Kernel 1: max_out = KSA_w @ deep + KSA_b  (per pixel), plus q (max over dd)
// and qmean (mean over dd).
// grid (HWD/128, B), block 128. Each thread owns one pixel p, 32 accumulators.
// ---------------------------------------------------------------------------
__global__ void k_maxout(const float* __restrict__ deep,
                         const float* __restrict__ ksa_w,
                         const float* __restrict__ ksa_b)
{
    __shared__ float ws[32 * 256];   // 32KB: half the weight matrix at a time
    int b = blockIdx.y;
    int p = blockIdx.x * 128 + threadIdx.x;

    float acc[32];
#pragma unroll
    for (int d = 0; d < 32; d++) acc[d] = ksa_b[d];

    for (int cc = 0; cc < C2; cc += 256) {
        __syncthreads();
        for (int i = threadIdx.x; i < 32 * 256; i += 128) {
            int d = i >> 8, c = i & 255;
            ws[i] = ksa_w[d * C2 + cc + c];
        }
        __syncthreads();
        const float* dptr = deep + ((size_t)b * C2 + cc) * HWD + p;
#pragma unroll 4
        for (int c = 0; c < 256; c++) {
            float x = dptr[(size_t)c * HWD];
#pragma unroll
            for (int d = 0; d < 32; d++) acc[d] += ws[d * 256 + c] * x;
        }
    }

    float mx = acc[0], sm = 0.f;
#pragma unroll
    for (int d = 0; d < 32; d++) {
        g_maxout[((size_t)b * DD + d) * HWD + p] = acc[d];
        mx = fmaxf(mx, acc[d]);
        sm += acc[d];
    }
    g_qmax [b * HWD + p] = mx;
    g_qmean[b * HWD + p] = sm * (1.f / 32.f);
}

// ---------------------------------------------------------------------------
// Kernel 2: lit (channel-scrambled flat-view dot), re_score, scale.
// One block per batch, 1024 threads (warp w handles lit[dd=w]).
// kt[p,dd] = maxout_flat[p*32+dd] = maxout[b, p>>7, ((p&127)<<5)+dd]
// ---------------------------------------------------------------------------
__global__ void k_lit(float* __restrict__ rescore_out)
{
    int b    = blockIdx.x;
    int tid  = threadIdx.x;
    int wid  = tid >> 5;
    int lane = tid & 31;
    const float* mo = g_maxout + (size_t)b * DD * HWD;
    const float* q  = g_qmax + b * HWD;

    float part = 0.f;
#pragma unroll 4
    for (int k = 0; k < 128; k++) {
        int p = lane + (k << 5);
        part += q[p] * mo[((p >> 7) << 12) + ((p & 127) << 5) + wid];
    }
#pragma unroll
    for (int off = 16; off; off >>= 1)
        part += __shfl_xor_sync(0xffffffffu, part, off);

    __shared__ float slit[32];
    if (lane == 0) slit[wid] = part * (1.f / 4096.f);
    __syncthreads();

    for (int p = tid; p < HWD; p += 1024) {
        float r = 0.f;
#pragma unroll
        for (int d = 0; d < 32; d++) r += slit[d] * mo[d * HWD + p];
        rescore_out[b * HWD + p] = r;
        g_scale[b * HWD + p] = 1.f + 1.f / (1.f + expf(-r));
    }
}

// ---------------------------------------------------------------------------
// Kernel 3: SGEMM per batch: Kx[o, pix] = K_w[o,c] @ shallow[c, pix] + K_b[o]
// M=256, N=16384, K=256. 128x128 tiles, BK=16, 8x8 per thread, 256 threads.
// ---------------------------------------------------------------------------
#define BM 128
#define BN 128
#define BK 16
__global__ __launch_bounds__(256, 2)
void k_sgemm(const float* __restrict__ W,
             const float* __restrict__ bias,
             const float* __restrict__ X)
{
    __shared__ float As[BK][BM + 4];   // pitch 132 floats (16B aligned rows)
    __shared__ float Bs[BK][BN];

    int b  = blockIdx.z;
    int m0 = blockIdx.y * BM;
    int n0 = blockIdx.x * BN;
    const float* Xb = X + (size_t)b * CIN * PIX;
    float*       Cb = g_Kx + (size_t)b * OC * PIX;

    int tid = threadIdx.x;
    int tx  = tid & 15;       // n direction
    int ty  = tid >> 4;       // m direction

    float acc[8][8];
#pragma unroll
    for (int i = 0; i < 8; i++)
#pragma unroll
        for (int j = 0; j < 8; j++) acc[i][j] = 0.f;

    for (int k0 = 0; k0 < CIN; k0 += BK) {
        // Load A tile (128 rows x 16 k), transposed into As[k][m]
#pragma unroll
        for (int r = 0; r < 2; r++) {
            int f  = tid + r * 256;          // 0..511 float4 slots
            int m  = f >> 2;                 // 0..127
            int kq = (f & 3) << 2;           // 0,4,8,12
            float4 a = *reinterpret_cast<const float4*>(W + (size_t)(m0 + m) * CIN + k0 + kq);
            As[kq + 0][m] = a.x;
            As[kq + 1][m] = a.y;
            As[kq + 2][m] = a.z;
            As[kq + 3][m] = a.w;
        }
        // Load B tile (16 k x 128 n)
#pragma unroll
        for (int r = 0; r < 2; r++) {
            int f  = tid + r * 256;
            int k  = f >> 5;                 // 0..15
            int n4 = (f & 31) << 2;          // 0..124
            *reinterpret_cast<float4*>(&Bs[k][n4]) =
                *reinterpret_cast<const float4*>(Xb + (size_t)(k0 + k) * PIX + n0 + n4);
        }
        __syncthreads();

#pragma unroll
        for (int k = 0; k < BK; k++) {
            float4 a0 = *reinterpret_cast<const float4*>(&As[k][ty * 8]);
            float4 a1 = *reinterpret_cast<const float4*>(&As[k][ty * 8 + 4]);
            float4 b0 = *reinterpret_cast<const float4*>(&Bs[k][tx * 8]);
            float4 b1 = *reinterpret_cast<const float4*>(&Bs[k][tx * 8 + 4]);
            float ra[8] = {a0.x, a0.y, a0.z, a0.w, a1.x, a1.y, a1.z, a1.w};
            float rb[8] = {b0.x, b0.y, b0.z, b0.w, b1.x, b1.y, b1.z, b1.w};
#pragma unroll
            for (int i = 0; i < 8; i++)
#pragma unroll
                for (int j = 0; j < 8; j++) acc[i][j] += ra[i] * rb[j];
        }
        __syncthreads();
    }

#pragma unroll
    for (int i = 0; i < 8; i++) {
        int m = m0 + ty * 8 + i;
        float bi = bias[m];
        float4 o0 = make_float4(acc[i][0] + bi, acc[i][1] + bi, acc[i][2] + bi, acc[i][3] + bi);
        float4 o1 = make_float4(acc[i][4] + bi, acc[i][5] + bi, acc[i][6] + bi, acc[i][7] + bi);
        float* cp = Cb + (size_t)m * PIX + n0 + tx * 8;
        *reinterpret_cast<float4*>(cp)     = o0;
        *reinterpret_cast<float4*>(cp + 4) = o1;
    }
}

// ---------------------------------------------------------------------------
// Kernel 4: fused unfold(3x3, stride 2, pad 1) + softmax attention + gating.
// One thread per output element [b][o][y][x]. Zero-padded window positions
// contribute value 0 and logit 0 (they DO enter the softmax denominator).
// ---------------------------------------------------------------------------
__global__ void k_att(float* __restrict__ out)
{
    int idx = blockIdx.x * 256 + threadIdx.x;   // < B*OC*HWD
    int p = idx & (HWD - 1);
    int o = (idx >> 12) & (OC - 1);
    int b = idx >> 20;
    int y = p >> 6, x = p & 63;

    const float* base = g_Kx + ((size_t)(b * OC + o) << 14);
    float m  = g_qmean[(b << 12) + p];
    float sc = g_scale[(b << 12) + p];

    float v[9];
    int yy0 = 2 * y - 1, xx0 = 2 * x - 1;
#pragma unroll
    for (int i = 0; i < 3; i++) {
        int yy = yy0 + i;
#pragma unroll
        for (int j = 0; j < 3; j++) {
            int xx = xx0 + j;
            v[i * 3 + j] = (yy >= 0 && xx >= 0) ? base[(yy << 7) + xx] : 0.f;
        }
    }

    float L = m * v[0];
#pragma unroll
    for (int k = 1; k < 9; k++) L = fmaxf(L, m * v[k]);
    float s = 0.f, num = 0.f;
#pragma unroll
    for (int k = 0; k < 9; k++) {
        float e = expf(m * v[k] - L);
        s   += e;
        num += e * v[k];
    }
    out[idx] = sc * (num / s);   // att * (1 + sigmoid(re_score))
}

// ---------------------------------------------------------------------------
extern "C" void kernel_launch(void* const* d_in, const int* in_sizes, int n_in,
                              void* d_out, int out_size)
{
    const float* shallow = (const float*)d_in[0];
    const float* deep    = (const float*)d_in[1];
    const float* K_w     = (const float*)d_in[2];
    const float* K_b     = (const float*)d_in[3];
    const float* KSA_w   = (const float*)d_in[4];
    const float* KSA_b   = (const float*)d_in[5];
    float* out = (float*)d_out;

    // Output layout: [B,OC,64,64] main, then [B,1,64,64] re_score.
    float* rescore_out = out + (size_t)BB * OC * HWD;

    k_maxout<<<dim3(HWD / 128, BB), 128>>>(deep, KSA_w, KSA_b);
    k_lit<<<BB, 1024>>>(rescore_out);
    k_sgemm<<<dim3(PIX / BN, OC / BM, BB), 256>>>(K_w, K_b, shallow);
    k_att<<<(BB * OC * HWD) / 256, 256>>>(out);
}